// round 16
// baseline (speedup 1.0000x reference)
#include <cuda_runtime.h>
#include <cuda_bf16.h>

#define NB 4
#define NP 4096
#define NC 128
#define KN 16
#define FULLM 0xFFFFFFFFu
#define LOG2E 1.4426950408889634f

typedef unsigned int uint;
typedef unsigned short ushort;

// scratch (no allocations allowed)
__device__ int    g_knn[NB * NP * KN];
__device__ float4 g_c4[NB * NP];
__device__ float  g_y[NB * NP * NC];           // Y = g1_w @ phi(features)
__device__ float  g_a7[NC * 8];                // A7 = g1_w @ W7 (+g1_b), padded to 8
__device__ float  g_b2s[NC];                   // g2_b * log2e
__device__ float  g_zeros[NC];                 // zero bias (static zero-init)
// split weights: per (m, ks, tig) one uint4 = {H01, L01, H23, L23}
__device__ uint4 g_w1i[NC * 32];
__device__ uint4 g_w2i[NC * 32];               // pre-scaled by log2e
__device__ uint4 g_wpi[NC * 32];               // phi_w split

// fast packed f32->bf16x2 (low half = a, high half = b)
__device__ __forceinline__ uint cvt2bf(float a, float b) {
    uint r; asm("cvt.rn.bf16x2.f32 %0, %1, %2;" : "=r"(r) : "f"(b), "f"(a)); return r;
}
__device__ __forceinline__ uint bfpack(float a, float b) { return cvt2bf(a, b); }
__device__ __forceinline__ uint bfpack_lo(float a, float b) {
    uint hp = cvt2bf(a, b);
    float ha = __uint_as_float(hp << 16);
    float hb = __uint_as_float(hp & 0xFFFF0000u);
    return cvt2bf(a - ha, b - hb);
}
__device__ __forceinline__ float ex2f(float x) {
    float r; asm("ex2.approx.f32 %0, %1;" : "=f"(r) : "f"(x)); return r;
}

// split-layout ushort index for k-position p (0..15) within 16-block ks of row m
__device__ __forceinline__ int widx(int m, int ks, int p) {
    return (m * 32 + ks * 4 + (p >> 2)) * 8 + ((p & 3) >> 1) * 4 + (p & 1);
}

// ---------------------------------------------------------------------------
// setup: prep (blocks 0..63) + weight split (64..127) + a7 warp-per-ch (128..143)
// ---------------------------------------------------------------------------
__global__ __launch_bounds__(256) void setup_kernel(
    const float* __restrict__ coords,
    const float* __restrict__ g1w, const float* __restrict__ g2w,
    const float* __restrict__ pw,
    const float* __restrict__ g1b, const float* __restrict__ g2b,
    const float* __restrict__ psw, const float* __restrict__ psb,
    const float* __restrict__ s2w, const float* __restrict__ s2b)
{
    const int bk = blockIdx.x, t = threadIdx.x;
    if (bk < 64) {
        int i = bk * 256 + t;
        float x = coords[3 * i + 0], y = coords[3 * i + 1], z = coords[3 * i + 2];
        g_c4[i] = make_float4(x, y, z, x * x + y * y + z * z);
    } else if (bk < 128) {
        int i = (bk - 64) * 256 + t;
        int m = i >> 7, k = i & 127;
        int ks = k >> 4, ii = k & 15;
        int p = ((ii >> 1) & 3) * 4 + (ii & 1) + ((ii >> 3) << 1);
        int idx = widx(m, ks, p);                    // hi; lo at idx+2
        ushort* w1 = (ushort*)g_w1i;
        ushort* w2 = (ushort*)g_w2i;
        ushort* wp = (ushort*)g_wpi;
        float x; __nv_bfloat16 h;
        x = g1w[i]; h = __float2bfloat16(x);
        w1[idx]     = __bfloat16_as_ushort(h);
        w1[idx + 2] = __bfloat16_as_ushort(__float2bfloat16(x - __bfloat162float(h)));
        x = g2w[i] * LOG2E; h = __float2bfloat16(x);
        w2[idx]     = __bfloat16_as_ushort(h);
        w2[idx + 2] = __bfloat16_as_ushort(__float2bfloat16(x - __bfloat162float(h)));
        x = pw[i]; h = __float2bfloat16(x);
        wp[idx]     = __bfloat16_as_ushort(h);
        wp[idx + 2] = __bfloat16_as_ushort(__float2bfloat16(x - __bfloat162float(h)));
    } else {
        // a7: one WARP per channel; lanes sum coalesced strides of g1w row
        int ch   = (bk - 128) * 8 + (t >> 5);
        int lane = t & 31;
        float a0 = 0, a1 = 0, a2 = 0, a3 = 0, a4 = 0, a5 = 0, a6 = 0;
#pragma unroll
        for (int k = 0; k < 4; ++k) {
            int i = lane + 32 * k;
            float gv = g1w[ch * NC + i];
            a0 = fmaf(gv, -psw[i * 3 + 0], a0);
            a1 = fmaf(gv, -psw[i * 3 + 1], a1);
            a2 = fmaf(gv, -psw[i * 3 + 2], a2);
            a3 = fmaf(gv, s2w[i * 3 + 0], a3);
            a4 = fmaf(gv, s2w[i * 3 + 1], a4);
            a5 = fmaf(gv, s2w[i * 3 + 2], a5);
            a6 = fmaf(gv, s2b[i] - psb[i], a6);
        }
#pragma unroll
        for (int s = 16; s > 0; s >>= 1) {
            a0 += __shfl_xor_sync(FULLM, a0, s);
            a1 += __shfl_xor_sync(FULLM, a1, s);
            a2 += __shfl_xor_sync(FULLM, a2, s);
            a3 += __shfl_xor_sync(FULLM, a3, s);
            a4 += __shfl_xor_sync(FULLM, a4, s);
            a5 += __shfl_xor_sync(FULLM, a5, s);
            a6 += __shfl_xor_sync(FULLM, a6, s);
        }
        if (lane == 0) {
            g_a7[ch * 8 + 0] = a0; g_a7[ch * 8 + 1] = a1; g_a7[ch * 8 + 2] = a2;
            g_a7[ch * 8 + 3] = a3; g_a7[ch * 8 + 4] = a4; g_a7[ch * 8 + 5] = a5;
            g_a7[ch * 8 + 6] = a6 + g1b[ch];
            g_a7[ch * 8 + 7] = 0.0f;
            g_b2s[ch] = g2b[ch] * LOG2E;
        }
    }
}

// ---------------------------------------------------------------------------
// kNN: warp per query, 8 candidates per lane per step (unchanged, passing)
// ---------------------------------------------------------------------------
__device__ __forceinline__ void knn_insert(unsigned m, float d2, int ibase, int lane,
                                           float& lv, int& li, float& tau)
{
    while (m) {
        int src = __ffs(m) - 1; m &= m - 1;
        float v  = __shfl_sync(FULLM, d2, src);
        int   vi = ibase + src;
        if (v < tau) {
            unsigned le = __ballot_sync(FULLM, lv <= v) & 0xFFFFu;
            int pos = __popc(le);
            float upv = __shfl_up_sync(FULLM, lv, 1);
            int   upi = __shfl_up_sync(FULLM, li, 1);
            if (lane == pos)      { lv = v;   li = vi;  }
            else if (lane > pos)  { lv = upv; li = upi; }
            tau = __shfl_sync(FULLM, lv, 15);
        }
    }
}

__global__ __launch_bounds__(256) void knn_kernel()
{
    const int gw   = (blockIdx.x * blockDim.x + threadIdx.x) >> 5;
    const int lane = threadIdx.x & 31;
    const int b    = gw >> 12;
    const int q    = gw & (NP - 1);

    const float4* cb = g_c4 + b * NP;
    const float4  qc = cb[q];

    float lv  = 3.4e38f;
    int   li  = 0;
    float tau = 3.4e38f;

    for (int t = 0; t < NP / 256; ++t) {
        const int j0 = t * 256 + lane;
        float d2v[8];
#pragma unroll
        for (int k = 0; k < 8; ++k) {
            float4 c = __ldg(cb + j0 + 32 * k);
            d2v[k] = __fsub_rn(__fadd_rn(qc.w, c.w),
                               __fmul_rn(2.0f, qc.x * c.x + qc.y * c.y + qc.z * c.z));
        }
#pragma unroll
        for (int k = 0; k < 8; ++k)
            knn_insert(__ballot_sync(FULLM, d2v[k] < tau), d2v[k],
                       t * 256 + 32 * k, lane, lv, li, tau);
    }
    if (lane < KN) g_knn[((size_t)b * NP + q) * KN + lane] = li;
}

// ---------------------------------------------------------------------------
__device__ __forceinline__ void mma16816(float (&d)[4], uint a0, uint a1, uint a2, uint a3,
                                         uint b0, uint b1)
{
    asm volatile(
        "mma.sync.aligned.m16n8k16.row.col.f32.bf16.bf16.f32 "
        "{%0,%1,%2,%3}, {%4,%5,%6,%7}, {%8,%9}, {%0,%1,%2,%3};"
        : "+f"(d[0]), "+f"(d[1]), "+f"(d[2]), "+f"(d[3])
        : "r"(a0), "r"(a1), "r"(a2), "r"(a3), "r"(b0), "r"(b1));
}

#define ATT2_STRIDE 36   // uint4 per col row; conflict-free 576B stride

// layout per uint4: {H01, L01, H23, L23}
template <int NG>
__device__ __forceinline__ void gamma_mma(
    const uint4* __restrict__ W, const float* __restrict__ bias,
    const uint4* __restrict__ att2v, int M0, int n0, int gid, int tig,
    float d[2][NG][4][4])
{
#pragma unroll
    for (int mt = 0; mt < 2; ++mt) {
        float b0 = bias[M0 + mt * 16 + gid];
        float b1 = bias[M0 + mt * 16 + gid + 8];
#pragma unroll
        for (int ng = 0; ng < NG; ++ng)
#pragma unroll
        for (int nt = 0; nt < 4; ++nt) {
            d[mt][ng][nt][0] = b0; d[mt][ng][nt][1] = b0;
            d[mt][ng][nt][2] = b1; d[mt][ng][nt][3] = b1;
        }
    }
#pragma unroll
    for (int ks = 0; ks < 8; ++ks) {
        const int wo = ks * 4 + tig;
        uint4 A0 = W[(M0 + gid) * 32 + wo];
        uint4 A1 = W[(M0 + gid + 8) * 32 + wo];
        uint4 A2 = W[(M0 + 16 + gid) * 32 + wo];
        uint4 A3 = W[(M0 + 16 + gid + 8) * 32 + wo];
#pragma unroll
        for (int ng = 0; ng < NG; ++ng)
#pragma unroll
        for (int nt = 0; nt < 4; ++nt) {
            int n = n0 + ng * 32 + nt * 8 + gid;
            uint4 bv = att2v[n * ATT2_STRIDE + wo];
            mma16816(d[0][ng][nt], A0.x, A1.x, A0.z, A1.z, bv.x, bv.z);  // Hh*Bh
            mma16816(d[0][ng][nt], A0.x, A1.x, A0.z, A1.z, bv.y, bv.w);  // Hh*Bl
            mma16816(d[0][ng][nt], A0.y, A1.y, A0.w, A1.w, bv.x, bv.z);  // Hl*Bh
            mma16816(d[1][ng][nt], A2.x, A3.x, A2.z, A3.z, bv.x, bv.z);
            mma16816(d[1][ng][nt], A2.x, A3.x, A2.z, A3.z, bv.y, bv.w);
            mma16816(d[1][ng][nt], A2.y, A3.y, A2.w, A3.w, bv.x, bv.z);
        }
    }
}

// ---------------------------------------------------------------------------
// phi_kernel: Y = g1_w @ (phi_w @ f + phi_b). Block = 32 points (512 CTAs).
// ---------------------------------------------------------------------------
__global__ __launch_bounds__(128) void phi_kernel(const float* __restrict__ features,
                                                  const float* __restrict__ phi_b)
{
    __shared__ __align__(16) char fsm[32 * 576];
    uint4*  f2v = (uint4*)fsm;
    ushort* f2u = (ushort*)fsm;

    const int t     = threadIdx.x;
    const int pbase = blockIdx.x * 32;
    const float4* fv = (const float4*)(features + (size_t)pbase * NC);

#pragma unroll
    for (int it = 0; it < 8; ++it) {
        int li  = it * 128 + t;
        int col = li >> 5;
        int c4  = li & 31;
        float4 v = fv[li];
        int ch = c4 * 4;
        int ks = ch >> 4, ii = ch & 15;
        int p  = ((ii >> 1) & 3) * 4 + ((ii >> 3) << 1);
        int idx = col * 288 + (ks * 4 + (p >> 2)) * 8 + ((p & 3) >> 1) * 4;
        *(uint2*)&f2u[idx]     = make_uint2(bfpack(v.x, v.y), bfpack_lo(v.x, v.y));
        *(uint2*)&f2u[idx + 8] = make_uint2(bfpack(v.z, v.w), bfpack_lo(v.z, v.w));
    }
    __syncthreads();

    const int wid = t >> 5, lane = t & 31;
    const int gid = lane >> 2, tig = lane & 3;
    const int M0  = wid * 32;

    float d[2][1][4][4];
    gamma_mma<1>(g_wpi, phi_b, f2v, M0, 0, gid, tig, d);     // xi
    __syncthreads();

#pragma unroll
    for (int mt = 0; mt < 2; ++mt)
#pragma unroll
    for (int nt = 0; nt < 4; ++nt)
#pragma unroll
    for (int e = 0; e < 4; ++e) {
        float v = d[mt][0][nt][e];
        int n    = nt * 8 + 2 * tig + (e & 1);
        int mrow = M0 + mt * 16 + gid + 8 * (e >> 1);
        int ks2 = mrow >> 4, i2 = mrow & 15;
        int p2 = ((i2 >> 1) & 3) * 4 + (i2 & 1) + ((i2 >> 3) << 1);
        int idx = n * 288 + (ks2 * 4 + (p2 >> 2)) * 8 + ((p2 & 3) >> 1) * 4 + (p2 & 1);
        __nv_bfloat16 h = __float2bfloat16(v);
        f2u[idx]     = __bfloat16_as_ushort(h);
        f2u[idx + 2] = __bfloat16_as_ushort(__float2bfloat16(v - __bfloat162float(h)));
    }
    __syncthreads();

    gamma_mma<1>(g_w1i, g_zeros, f2v, M0, 0, gid, tig, d);   // Y = g1 @ xi

#pragma unroll
    for (int mt = 0; mt < 2; ++mt)
#pragma unroll
    for (int nt = 0; nt < 4; ++nt) {
        int m = M0 + mt * 16 + gid;
        int n = nt * 8 + 2 * tig;
        size_t r0 = (size_t)(pbase + n) * NC;
        g_y[r0 + m]            = d[mt][0][nt][0];
        g_y[r0 + NC + m]       = d[mt][0][nt][1];
        g_y[r0 + m + 8]        = d[mt][0][nt][2];
        g_y[r0 + NC + m + 8]   = d[mt][0][nt][3];
    }
}

// ---------------------------------------------------------------------------
// Fused point-transformer. Block = 8 points (128 cols), 256 threads, 8 warps.
// ---------------------------------------------------------------------------
#define SM_ATT2 0                        // uint4 [128][36] = 73728; aliased by att_f
#define SM_G    73728                    // gsh float4 [128*2] = 4096
#define SM_SMP  (SM_G + 4096)            // float [4][128] = 2048
#define SM_SMS  (SM_SMP + 2048)          // float [4][128] = 2048
#define SM_SMI  (SM_SMS + 2048)          // float [128]
#define SM_TOTAL (SM_SMI + 512)

__global__ __launch_bounds__(256, 2) void pt_kernel(
    const float* __restrict__ s1_w,   const float* __restrict__ s1_b,
    const float* __restrict__ s2_w,   const float* __restrict__ s2_b,
    const float* __restrict__ alpha_w, const float* __restrict__ alpha_b,
    float* __restrict__ out)
{
    extern __shared__ __align__(16) char sm[];
    uint4*  att2v = (uint4*)(sm + SM_ATT2);
    ushort* att2u = (ushort*)(sm + SM_ATT2);            // row stride 288 ushorts
    float (*att_f)[130] = (float(*)[130])(sm + SM_ATT2); // alias (att2 dead by then)
    float4* gsh        = (float4*)(sm + SM_G);          // [128][2] float4
    float (*smp4)[128] = (float(*)[128])(sm + SM_SMP);
    float (*sms4)[128] = (float(*)[128])(sm + SM_SMS);
    float* sminv       = (float*)(sm + SM_SMI);

    const int t    = threadIdx.x;
    const int c    = t & 63;
    const int cg   = t >> 6;              // 0..3 -> cols cg*32..+31
    const int pn0  = blockIdx.x * 8;
    const int b    = pn0 >> 12;
    const int n0_  = pn0 & (NP - 1);
    const int base = b * NP + n0_;

    // ---- t<128 computes g directly (own coord loads) ----
    if (t < 128) {
        int p  = t >> 4;
        int id = g_knn[(size_t)(base + p) * KN + (t & 15)];
        float4 cc = g_c4[b * NP + id];
        float4 qv = g_c4[base + p];
        float rx = qv.x - cc.x, ry = qv.y - cc.y, rz = qv.z - cc.z;
        float h0 = fmaxf(s1_w[0] * rx + s1_w[1] * ry + s1_w[2] * rz + s1_b[0], 0.0f);
        float h1 = fmaxf(s1_w[3] * rx + s1_w[4] * ry + s1_w[5] * rz + s1_b[1], 0.0f);
        float h2 = fmaxf(s1_w[6] * rx + s1_w[7] * ry + s1_w[8] * rz + s1_b[2], 0.0f);
        gsh[t * 2]     = make_float4(cc.x, cc.y, cc.z, h0);
        gsh[t * 2 + 1] = make_float4(h1, h2, 1.0f, 0.0f);
    }
    // ---- Y loads: direct per-thread float2 (coalesced) ----
    const int ch0 = 2 * c, ch1 = 2 * c + 1;
    float2 ya = *(const float2*)&g_y[(size_t)(base + 2 * cg) * NC + ch0];     // (y00,y10)
    float2 yb = *(const float2*)&g_y[(size_t)(base + 2 * cg + 1) * NC + ch0]; // (y01,y11)
    __syncthreads();

    // ---- layer 1 (folded): l1 = relu(A7.g + Y), split into att2 (uint2 store) ----
    {
        const float4* a7v = (const float4*)g_a7;
        float4 a0l = a7v[ch0 * 2], a0h = a7v[ch0 * 2 + 1];
        float4 a1l = a7v[ch1 * 2], a1h = a7v[ch1 * 2 + 1];
        const float y00 = ya.x, y10 = ya.y, y01 = yb.x, y11 = yb.y;
        const int ksq = ch0 >> 4;
        const int iq  = ch0 & 15;                              // even
        const int pq  = ((iq >> 1) & 3) * 4 + ((iq >> 3) << 1);
        const int hbase = (ksq * 4 + (pq >> 2)) * 8 + ((pq & 3) >> 1) * 4;
#pragma unroll
        for (int jj = 0; jj < 32; ++jj) {
            int col = cg * 32 + jj;
            float4 gl = gsh[col * 2], gh = gsh[col * 2 + 1];
            float v0 = a0l.x * gl.x + a0l.y * gl.y + a0l.z * gl.z + a0l.w * gl.w
                     + a0h.x * gh.x + a0h.y * gh.y + a0h.z
                     + ((jj & 16) ? y01 : y00);
            float v1 = a1l.x * gl.x + a1l.y * gl.y + a1l.z * gl.z + a1l.w * gl.w
                     + a1h.x * gh.x + a1h.y * gh.y + a1h.z
                     + ((jj & 16) ? y11 : y10);
            v0 = fmaxf(v0, 0.0f);
            v1 = fmaxf(v1, 0.0f);
            uint hp = cvt2bf(v0, v1);
            float h0f = __uint_as_float(hp << 16);
            float h1f = __uint_as_float(hp & 0xFFFF0000u);
            uint lp = cvt2bf(v0 - h0f, v1 - h1f);
            *(uint2*)&att2u[col * 288 + hbase] = make_uint2(hp, lp);
        }
    }
    __syncthreads();

    const int wid = t >> 5, lane = t & 31;
    const int gid = lane >> 2, tig = lane & 3;
    const int M0  = (wid & 3) * 32;
    const int nc0 = (wid >> 2) * 64;

    {
        float d[2][2][4][4];

        // ===== gamma layer 2 (MMA, weights pre-scaled by log2e) =====
        gamma_mma<2>(g_w2i, g_b2s, att2v, M0, nc0, gid, tig, d);
        __syncthreads();   // att2 fully read by ALL warps before aliased overwrite
#pragma unroll
        for (int mt = 0; mt < 2; ++mt)
#pragma unroll
        for (int ng = 0; ng < 2; ++ng)
#pragma unroll
        for (int nt = 0; nt < 4; ++nt) {
            int m = M0 + mt * 16 + gid;
            int n = nc0 + ng * 32 + nt * 8 + 2 * tig;
            *(float2*)&att_f[m][n]     = make_float2(d[mt][ng][nt][0], d[mt][ng][nt][1]);
            *(float2*)&att_f[m + 8][n] = make_float2(d[mt][ng][nt][2], d[mt][ng][nt][3]);
        }
    }
    __syncthreads();

    // ---- softmax over channels: float2 col-pairs, 4 row-groups, raw ex2 ----
    {
        const int cp = t & 63, h = t >> 6;   // col pair, 32-row group
        const int col = 2 * cp;
        float m0 = -3.4e38f, m1 = -3.4e38f;
#pragma unroll 8
        for (int i = h * 32; i < h * 32 + 32; ++i) {
            float2 v = *(float2*)&att_f[i][col];
            m0 = fmaxf(m0, v.x); m1 = fmaxf(m1, v.y);
        }
        *(float2*)&smp4[h][col] = make_float2(m0, m1);
        __syncthreads();
        float2 p0 = *(float2*)&smp4[0][col];
        float2 p1 = *(float2*)&smp4[1][col];
        float2 p2 = *(float2*)&smp4[2][col];
        float2 p3 = *(float2*)&smp4[3][col];
        float mmx = fmaxf(fmaxf(p0.x, p1.x), fmaxf(p2.x, p3.x));
        float mmy = fmaxf(fmaxf(p0.y, p1.y), fmaxf(p2.y, p3.y));
        float s0 = 0.0f, s1 = 0.0f;
#pragma unroll 4
        for (int i = h * 32; i < h * 32 + 32; ++i) {
            float2 v = *(float2*)&att_f[i][col];
            float e0 = ex2f(v.x - mmx);
            float e1 = ex2f(v.y - mmy);
            *(float2*)&att_f[i][col] = make_float2(e0, e1);
            s0 += e0; s1 += e1;
        }
        *(float2*)&sms4[h][col] = make_float2(s0, s1);
        __syncthreads();
        if (h == 0) {
            float2 q0 = *(float2*)&sms4[0][col];
            float2 q1 = *(float2*)&sms4[1][col];
            float2 q2 = *(float2*)&sms4[2][col];
            float2 q3 = *(float2*)&sms4[3][col];
            sminv[col]     = 1.0f / (q0.x + q1.x + q2.x + q3.x);
            sminv[col + 1] = 1.0f / (q0.y + q1.y + q2.y + q3.y);
        }
        __syncthreads();
    }

    // ---- epilogue: out = sum_k softmax * (V7.g), col-pairs, float2 loads ----
    {
        const int oa = c, ob = c + 64;
        const float aa0 = alpha_w[oa * 3], aa1 = alpha_w[oa * 3 + 1], aa2 = alpha_w[oa * 3 + 2];
        const float ab0 = alpha_w[ob * 3], ab1 = alpha_w[ob * 3 + 1], ab2 = alpha_w[ob * 3 + 2];
        const float s2a0 = s2_w[oa * 3], s2a1 = s2_w[oa * 3 + 1], s2a2 = s2_w[oa * 3 + 2];
        const float s2b0 = s2_w[ob * 3], s2b1 = s2_w[ob * 3 + 1], s2b2 = s2_w[ob * 3 + 2];
        const float ca = alpha_b[oa] + s2_b[oa];
        const float cb = alpha_b[ob] + s2_b[ob];

        float o0a = 0.0f, o1a = 0.0f, o0b = 0.0f, o1b = 0.0f;
#pragma unroll
        for (int j2 = 0; j2 < 16; ++j2) {
            int col = cg * 32 + 2 * j2;
            float4 gl0 = gsh[col * 2],     gh0 = gsh[col * 2 + 1];
            float4 gl1 = gsh[col * 2 + 2], gh1 = gsh[col * 2 + 3];
            float va0 = aa0 * gl0.x + aa1 * gl0.y + aa2 * gl0.z + s2a0 * gl0.w
                      + s2a1 * gh0.x + s2a2 * gh0.y + ca;
            float vb0 = ab0 * gl0.x + ab1 * gl0.y + ab2 * gl0.z + s2b0 * gl0.w
                      + s2b1 * gh0.x + s2b2 * gh0.y + cb;
            float va1 = aa0 * gl1.x + aa1 * gl1.y + aa2 * gl1.z + s2a0 * gl1.w
                      + s2a1 * gh1.x + s2a2 * gh1.y + ca;
            float vb1 = ab0 * gl1.x + ab1 * gl1.y + ab2 * gl1.z + s2b0 * gl1.w
                      + s2b1 * gh1.x + s2b2 * gh1.y + cb;
            float2 iv = *(float2*)&sminv[col];
            float2 ea = *(float2*)&att_f[oa][col];
            float2 eb = *(float2*)&att_f[ob][col];
            float pa = ea.x * iv.x * va0 + ea.y * iv.y * va1;
            float pb = eb.x * iv.x * vb0 + eb.y * iv.y * vb1;
            if (j2 < 8) { o0a += pa; o0b += pb; }
            else        { o1a += pa; o1b += pb; }
        }
        int p0 = cg * 2;
        out[(size_t)(base + p0) * NC + oa]     = o0a;
        out[(size_t)(base + p0) * NC + ob]     = o0b;
        out[(size_t)(base + p0 + 1) * NC + oa] = o1a;
        out[(size_t)(base + p0 + 1) * NC + ob] = o1b;
    }
}

// ---------------------------------------------------------------------------
extern "C" void kernel_launch(void* const* d_in, const int* in_sizes, int n_in,
                              void* d_out, int out_size)
{
    const float* coords   = (const float*)d_in[0];
    const float* features = (const float*)d_in[1];
    const float* phi_w    = (const float*)d_in[2];
    const float* phi_b    = (const float*)d_in[3];
    const float* psi_w    = (const float*)d_in[4];
    const float* psi_b    = (const float*)d_in[5];
    const float* g1_w     = (const float*)d_in[6];
    const float* g1_b     = (const float*)d_in[7];
    const float* g2_w     = (const float*)d_in[8];
    const float* g2_b     = (const float*)d_in[9];
    const float* s1_w     = (const float*)d_in[10];
    const float* s1_b     = (const float*)d_in[11];
    const float* s2_w     = (const float*)d_in[12];
    const float* s2_b     = (const float*)d_in[13];
    const float* alpha_w  = (const float*)d_in[14];
    const float* alpha_b  = (const float*)d_in[15];
    float* out = (float*)d_out;

    cudaFuncSetAttribute(pt_kernel, cudaFuncAttributeMaxDynamicSharedMemorySize, SM_TOTAL);

    setup_kernel<<<144, 256>>>(coords, g1_w, g2_w, phi_w,
                               g1_b, g2_b, psi_w, psi_b, s2_w, s2_b);
    phi_kernel<<<NB * NP / 32, 128>>>(features, phi_b);
    knn_kernel<<<NB * NP * 32 / 256, 256>>>();
    pt_kernel<<<NB * NP / 8, 256, SM_TOTAL>>>(s1_w, s1_b,
                                              s2_w, s2_b, alpha_w, alpha_b, out);
}

// round 17
// speedup vs baseline: 1.0380x; 1.0380x over previous
#include <cuda_runtime.h>
#include <cuda_bf16.h>

#define NB 4
#define NP 4096
#define NC 128
#define KN 16
#define FULLM 0xFFFFFFFFu
#define LOG2E 1.4426950408889634f

typedef unsigned int uint;
typedef unsigned short ushort;

// scratch (no allocations allowed)
__device__ int    g_knn[NB * NP * KN];
__device__ float4 g_c4[NB * NP];
__device__ float  g_y[NB * NP * NC];           // Y = g1_w @ phi(features)
__device__ float  g_a7[NC * 8];                // A7 = g1_w @ W7 (+g1_b), padded to 8
__device__ float  g_b2s[NC];                   // g2_b * log2e
__device__ float  g_zeros[NC];                 // zero bias (static zero-init)
// interleaved split weights: per (m, ks, tig) one uint4 = {H01, H23, L01, L23}
__device__ uint4 g_w1i[NC * 32];
__device__ uint4 g_w2i[NC * 32];               // pre-scaled by log2e
__device__ uint4 g_wpi[NC * 32];               // phi_w split

// fast packed f32->bf16x2 (low half = a, high half = b)
__device__ __forceinline__ uint cvt2bf(float a, float b) {
    uint r; asm("cvt.rn.bf16x2.f32 %0, %1, %2;" : "=r"(r) : "f"(b), "f"(a)); return r;
}
__device__ __forceinline__ uint bfpack(float a, float b) { return cvt2bf(a, b); }
__device__ __forceinline__ uint bfpack_lo(float a, float b) {
    uint hp = cvt2bf(a, b);
    float ha = __uint_as_float(hp << 16);
    float hb = __uint_as_float(hp & 0xFFFF0000u);
    return cvt2bf(a - ha, b - hb);
}
__device__ __forceinline__ float ex2f(float x) {
    float r; asm("ex2.approx.f32 %0, %1;" : "=f"(r) : "f"(x)); return r;
}

// ---------------------------------------------------------------------------
// setup: prep (blocks 0..63) + weight split (64..127) + a7 warp-per-ch (128..143)
// ---------------------------------------------------------------------------
__global__ __launch_bounds__(256) void setup_kernel(
    const float* __restrict__ coords,
    const float* __restrict__ g1w, const float* __restrict__ g2w,
    const float* __restrict__ pw,
    const float* __restrict__ g1b, const float* __restrict__ g2b,
    const float* __restrict__ psw, const float* __restrict__ psb,
    const float* __restrict__ s2w, const float* __restrict__ s2b)
{
    const int bk = blockIdx.x, t = threadIdx.x;
    if (bk < 64) {
        int i = bk * 256 + t;
        float x = coords[3 * i + 0], y = coords[3 * i + 1], z = coords[3 * i + 2];
        g_c4[i] = make_float4(x, y, z, x * x + y * y + z * z);
    } else if (bk < 128) {
        int i = (bk - 64) * 256 + t;
        int m = i >> 7, k = i & 127;
        int ks = k >> 4, ii = k & 15;
        int p = ((ii >> 1) & 3) * 4 + (ii & 1) + ((ii >> 3) << 1);
        int idx = (m * 32 + ks * 4 + (p >> 2)) * 8 + (p & 3);
        ushort* w1 = (ushort*)g_w1i;
        ushort* w2 = (ushort*)g_w2i;
        ushort* wp = (ushort*)g_wpi;
        float x; __nv_bfloat16 h;
        x = g1w[i]; h = __float2bfloat16(x);
        w1[idx] = __bfloat16_as_ushort(h);
        w1[idx + 4] = __bfloat16_as_ushort(__float2bfloat16(x - __bfloat162float(h)));
        x = g2w[i] * LOG2E; h = __float2bfloat16(x);
        w2[idx] = __bfloat16_as_ushort(h);
        w2[idx + 4] = __bfloat16_as_ushort(__float2bfloat16(x - __bfloat162float(h)));
        x = pw[i]; h = __float2bfloat16(x);
        wp[idx] = __bfloat16_as_ushort(h);
        wp[idx + 4] = __bfloat16_as_ushort(__float2bfloat16(x - __bfloat162float(h)));
    } else {
        // a7: one WARP per channel; lanes sum coalesced strides of g1w row
        int ch   = (bk - 128) * 8 + (t >> 5);
        int lane = t & 31;
        float a0 = 0, a1 = 0, a2 = 0, a3 = 0, a4 = 0, a5 = 0, a6 = 0;
#pragma unroll
        for (int k = 0; k < 4; ++k) {
            int i = lane + 32 * k;
            float gv = g1w[ch * NC + i];
            a0 = fmaf(gv, -psw[i * 3 + 0], a0);
            a1 = fmaf(gv, -psw[i * 3 + 1], a1);
            a2 = fmaf(gv, -psw[i * 3 + 2], a2);
            a3 = fmaf(gv, s2w[i * 3 + 0], a3);
            a4 = fmaf(gv, s2w[i * 3 + 1], a4);
            a5 = fmaf(gv, s2w[i * 3 + 2], a5);
            a6 = fmaf(gv, s2b[i] - psb[i], a6);
        }
#pragma unroll
        for (int s = 16; s > 0; s >>= 1) {
            a0 += __shfl_xor_sync(FULLM, a0, s);
            a1 += __shfl_xor_sync(FULLM, a1, s);
            a2 += __shfl_xor_sync(FULLM, a2, s);
            a3 += __shfl_xor_sync(FULLM, a3, s);
            a4 += __shfl_xor_sync(FULLM, a4, s);
            a5 += __shfl_xor_sync(FULLM, a5, s);
            a6 += __shfl_xor_sync(FULLM, a6, s);
        }
        if (lane == 0) {
            g_a7[ch * 8 + 0] = a0; g_a7[ch * 8 + 1] = a1; g_a7[ch * 8 + 2] = a2;
            g_a7[ch * 8 + 3] = a3; g_a7[ch * 8 + 4] = a4; g_a7[ch * 8 + 5] = a5;
            g_a7[ch * 8 + 6] = a6 + g1b[ch];
            g_a7[ch * 8 + 7] = 0.0f;
            g_b2s[ch] = g2b[ch] * LOG2E;
        }
    }
}

// ---------------------------------------------------------------------------
// kNN: warp per query, 8 candidates per lane per step (16 outer iterations).
// Groups processed sequentially in ascending index order (top_k tie order).
// ---------------------------------------------------------------------------
__device__ __forceinline__ void knn_insert(unsigned m, float d2, int ibase, int lane,
                                           float& lv, int& li, float& tau)
{
    while (m) {
        int src = __ffs(m) - 1; m &= m - 1;
        float v  = __shfl_sync(FULLM, d2, src);
        int   vi = ibase + src;
        if (v < tau) {
            unsigned le = __ballot_sync(FULLM, lv <= v) & 0xFFFFu;
            int pos = __popc(le);
            float upv = __shfl_up_sync(FULLM, lv, 1);
            int   upi = __shfl_up_sync(FULLM, li, 1);
            if (lane == pos)      { lv = v;   li = vi;  }
            else if (lane > pos)  { lv = upv; li = upi; }
            tau = __shfl_sync(FULLM, lv, 15);
        }
    }
}

__global__ __launch_bounds__(256) void knn_kernel()
{
    const int gw   = (blockIdx.x * blockDim.x + threadIdx.x) >> 5;
    const int lane = threadIdx.x & 31;
    const int b    = gw >> 12;
    const int q    = gw & (NP - 1);

    const float4* cb = g_c4 + b * NP;
    const float4  qc = cb[q];

    float lv  = 3.4e38f;
    int   li  = 0;
    float tau = 3.4e38f;

    for (int t = 0; t < NP / 256; ++t) {
        const int j0 = t * 256 + lane;
        float d2v[8];
#pragma unroll
        for (int k = 0; k < 8; ++k) {
            float4 c = __ldg(cb + j0 + 32 * k);
            d2v[k] = __fsub_rn(__fadd_rn(qc.w, c.w),
                               __fmul_rn(2.0f, qc.x * c.x + qc.y * c.y + qc.z * c.z));
        }
#pragma unroll
        for (int k = 0; k < 8; ++k)
            knn_insert(__ballot_sync(FULLM, d2v[k] < tau), d2v[k],
                       t * 256 + 32 * k, lane, lv, li, tau);
    }
    if (lane < KN) g_knn[((size_t)b * NP + q) * KN + lane] = li;
}

// ---------------------------------------------------------------------------
__device__ __forceinline__ void mma16816(float (&d)[4], uint a0, uint a1, uint a2, uint a3,
                                         uint b0, uint b1)
{
    asm volatile(
        "mma.sync.aligned.m16n8k16.row.col.f32.bf16.bf16.f32 "
        "{%0,%1,%2,%3}, {%4,%5,%6,%7}, {%8,%9}, {%0,%1,%2,%3};"
        : "+f"(d[0]), "+f"(d[1]), "+f"(d[2]), "+f"(d[3])
        : "r"(a0), "r"(a1), "r"(a2), "r"(a3), "r"(b0), "r"(b1));
}

#define ATT2_STRIDE 36   // uint4 per col row; conflict-free 576B stride

template <int NG>
__device__ __forceinline__ void gamma_mma(
    const uint4* __restrict__ W, const float* __restrict__ bias,
    const uint4* __restrict__ att2v, int M0, int n0, int gid, int tig,
    float d[2][NG][4][4])
{
#pragma unroll
    for (int mt = 0; mt < 2; ++mt) {
        float b0 = bias[M0 + mt * 16 + gid];
        float b1 = bias[M0 + mt * 16 + gid + 8];
#pragma unroll
        for (int ng = 0; ng < NG; ++ng)
#pragma unroll
        for (int nt = 0; nt < 4; ++nt) {
            d[mt][ng][nt][0] = b0; d[mt][ng][nt][1] = b0;
            d[mt][ng][nt][2] = b1; d[mt][ng][nt][3] = b1;
        }
    }
#pragma unroll
    for (int ks = 0; ks < 8; ++ks) {
        const int wo = ks * 4 + tig;
        uint4 A0 = W[(M0 + gid) * 32 + wo];
        uint4 A1 = W[(M0 + gid + 8) * 32 + wo];
        uint4 A2 = W[(M0 + 16 + gid) * 32 + wo];
        uint4 A3 = W[(M0 + 16 + gid + 8) * 32 + wo];
#pragma unroll
        for (int ng = 0; ng < NG; ++ng)
#pragma unroll
        for (int nt = 0; nt < 4; ++nt) {
            int n = n0 + ng * 32 + nt * 8 + gid;
            uint4 bv = att2v[n * ATT2_STRIDE + wo];
            mma16816(d[0][ng][nt], A0.x, A1.x, A0.y, A1.y, bv.x, bv.y);  // Hh*Bh
            mma16816(d[0][ng][nt], A0.x, A1.x, A0.y, A1.y, bv.z, bv.w);  // Hh*Bl
            mma16816(d[0][ng][nt], A0.z, A1.z, A0.w, A1.w, bv.x, bv.y);  // Hl*Bh
            mma16816(d[1][ng][nt], A2.x, A3.x, A2.y, A3.y, bv.x, bv.y);
            mma16816(d[1][ng][nt], A2.x, A3.x, A2.y, A3.y, bv.z, bv.w);
            mma16816(d[1][ng][nt], A2.z, A3.z, A2.w, A3.w, bv.x, bv.y);
        }
    }
}

// ---------------------------------------------------------------------------
// phi_kernel: Y = g1_w @ (phi_w @ f + phi_b). Block = 32 points (512 CTAs).
// ---------------------------------------------------------------------------
__global__ __launch_bounds__(128) void phi_kernel(const float* __restrict__ features,
                                                  const float* __restrict__ phi_b)
{
    __shared__ __align__(16) char fsm[32 * 576];
    uint4*  f2v = (uint4*)fsm;
    ushort* f2u = (ushort*)fsm;

    const int t     = threadIdx.x;
    const int pbase = blockIdx.x * 32;
    const float4* fv = (const float4*)(features + (size_t)pbase * NC);

#pragma unroll
    for (int it = 0; it < 8; ++it) {
        int li  = it * 128 + t;
        int col = li >> 5;
        int c4  = li & 31;
        float4 v = fv[li];
        int ch = c4 * 4;
        int ks = ch >> 4, ii = ch & 15;
        int p  = ((ii >> 1) & 3) * 4 + ((ii >> 3) << 1);
        int idx = col * 288 + (ks * 4 + (p >> 2)) * 8 + (p & 3);
        *(uint*)&f2u[idx]      = bfpack(v.x, v.y);
        *(uint*)&f2u[idx + 4]  = bfpack_lo(v.x, v.y);
        *(uint*)&f2u[idx + 8]  = bfpack(v.z, v.w);
        *(uint*)&f2u[idx + 12] = bfpack_lo(v.z, v.w);
    }
    __syncthreads();

    const int wid = t >> 5, lane = t & 31;
    const int gid = lane >> 2, tig = lane & 3;
    const int M0  = wid * 32;

    float d[2][1][4][4];
    gamma_mma<1>(g_wpi, phi_b, f2v, M0, 0, gid, tig, d);     // xi
    __syncthreads();

#pragma unroll
    for (int mt = 0; mt < 2; ++mt)
#pragma unroll
    for (int nt = 0; nt < 4; ++nt)
#pragma unroll
    for (int e = 0; e < 4; ++e) {
        float v = d[mt][0][nt][e];
        int n    = nt * 8 + 2 * tig + (e & 1);
        int mrow = M0 + mt * 16 + gid + 8 * (e >> 1);
        int ks2 = mrow >> 4, i2 = mrow & 15;
        int p2 = ((i2 >> 1) & 3) * 4 + (i2 & 1) + ((i2 >> 3) << 1);
        int idx = n * 288 + (ks2 * 4 + (p2 >> 2)) * 8 + (p2 & 3);
        __nv_bfloat16 h = __float2bfloat16(v);
        f2u[idx]     = __bfloat16_as_ushort(h);
        f2u[idx + 4] = __bfloat16_as_ushort(__float2bfloat16(v - __bfloat162float(h)));
    }
    __syncthreads();

    gamma_mma<1>(g_w1i, g_zeros, f2v, M0, 0, gid, tig, d);   // Y = g1 @ xi

#pragma unroll
    for (int mt = 0; mt < 2; ++mt)
#pragma unroll
    for (int nt = 0; nt < 4; ++nt) {
        int m = M0 + mt * 16 + gid;
        int n = nt * 8 + 2 * tig;
        size_t r0 = (size_t)(pbase + n) * NC;
        g_y[r0 + m]            = d[mt][0][nt][0];
        g_y[r0 + NC + m]       = d[mt][0][nt][1];
        g_y[r0 + m + 8]        = d[mt][0][nt][2];
        g_y[r0 + NC + m + 8]   = d[mt][0][nt][3];
    }
}

// ---------------------------------------------------------------------------
// Fused point-transformer. Block = 8 points (128 cols), 256 threads, 8 warps.
// Layer 1 folded scalar; layer 2 MMA (log2e-folded); raw-ex2 softmax.
// ---------------------------------------------------------------------------
#define SM_ATT2 0                        // uint4 [128][36] = 73728; aliased by att_f
#define SM_G    73728                    // gsh float4 [128*2] = 4096
#define SM_SMP  (SM_G + 4096)            // float [4][128] = 2048
#define SM_SMS  (SM_SMP + 2048)          // float [4][128] = 2048
#define SM_SMI  (SM_SMS + 2048)          // float [128]
#define SM_TOTAL (SM_SMI + 512)

__global__ __launch_bounds__(256, 2) void pt_kernel(
    const float* __restrict__ s1_w,   const float* __restrict__ s1_b,
    const float* __restrict__ s2_w,   const float* __restrict__ s2_b,
    const float* __restrict__ alpha_w, const float* __restrict__ alpha_b,
    float* __restrict__ out)
{
    extern __shared__ __align__(16) char sm[];
    uint4*  att2v = (uint4*)(sm + SM_ATT2);
    ushort* att2u = (ushort*)(sm + SM_ATT2);            // row stride 288 ushorts
    float (*att_f)[130] = (float(*)[130])(sm + SM_ATT2); // alias (att2 dead by then)
    float4* gsh        = (float4*)(sm + SM_G);          // [128][2] float4
    float (*smp4)[128] = (float(*)[128])(sm + SM_SMP);
    float (*sms4)[128] = (float(*)[128])(sm + SM_SMS);
    float* sminv       = (float*)(sm + SM_SMI);

    const int t    = threadIdx.x;
    const int c    = t & 63;
    const int cg   = t >> 6;              // 0..3 -> cols cg*32..+31
    const int pn0  = blockIdx.x * 8;
    const int b    = pn0 >> 12;
    const int n0_  = pn0 & (NP - 1);
    const int base = b * NP + n0_;

    // ---- t<128 computes g directly (own coord loads) ----
    if (t < 128) {
        int p  = t >> 4;
        int id = g_knn[(size_t)(base + p) * KN + (t & 15)];
        float4 cc = g_c4[b * NP + id];
        float4 qv = g_c4[base + p];
        float rx = qv.x - cc.x, ry = qv.y - cc.y, rz = qv.z - cc.z;
        float h0 = fmaxf(s1_w[0] * rx + s1_w[1] * ry + s1_w[2] * rz + s1_b[0], 0.0f);
        float h1 = fmaxf(s1_w[3] * rx + s1_w[4] * ry + s1_w[5] * rz + s1_b[1], 0.0f);
        float h2 = fmaxf(s1_w[6] * rx + s1_w[7] * ry + s1_w[8] * rz + s1_b[2], 0.0f);
        gsh[t * 2]     = make_float4(cc.x, cc.y, cc.z, h0);
        gsh[t * 2 + 1] = make_float4(h1, h2, 1.0f, 0.0f);
    }
    // ---- Y loads: direct per-thread float2 (coalesced) ----
    const int ch0 = 2 * c, ch1 = 2 * c + 1;
    float2 ya = *(const float2*)&g_y[(size_t)(base + 2 * cg) * NC + ch0];     // (y00,y10)
    float2 yb = *(const float2*)&g_y[(size_t)(base + 2 * cg + 1) * NC + ch0]; // (y01,y11)
    __syncthreads();

    // ---- layer 1 (folded): l1 = relu(A7.g + Y), split into att2 ----
    {
        const float4* a7v = (const float4*)g_a7;
        float4 a0l = a7v[ch0 * 2], a0h = a7v[ch0 * 2 + 1];
        float4 a1l = a7v[ch1 * 2], a1h = a7v[ch1 * 2 + 1];
        const float y00 = ya.x, y10 = ya.y, y01 = yb.x, y11 = yb.y;
        const int ksq = ch0 >> 4;
        const int iq  = ch0 & 15;                              // even
        const int pq  = ((iq >> 1) & 3) * 4 + ((iq >> 3) << 1);
        const int hbase = (ksq * 4 + (pq >> 2)) * 8 + (pq & 3);
#pragma unroll
        for (int jj = 0; jj < 32; ++jj) {
            int col = cg * 32 + jj;
            float4 gl = gsh[col * 2], gh = gsh[col * 2 + 1];
            float v0 = a0l.x * gl.x + a0l.y * gl.y + a0l.z * gl.z + a0l.w * gl.w
                     + a0h.x * gh.x + a0h.y * gh.y + a0h.z
                     + ((jj & 16) ? y01 : y00);
            float v1 = a1l.x * gl.x + a1l.y * gl.y + a1l.z * gl.z + a1l.w * gl.w
                     + a1h.x * gh.x + a1h.y * gh.y + a1h.z
                     + ((jj & 16) ? y11 : y10);
            v0 = fmaxf(v0, 0.0f);
            v1 = fmaxf(v1, 0.0f);
            uint hp = cvt2bf(v0, v1);
            float h0f = __uint_as_float(hp << 16);
            float h1f = __uint_as_float(hp & 0xFFFF0000u);
            uint lp = cvt2bf(v0 - h0f, v1 - h1f);
            int idx = col * 288 + hbase;
            *(uint*)&att2u[idx]     = hp;
            *(uint*)&att2u[idx + 4] = lp;
        }
    }
    __syncthreads();

    const int wid = t >> 5, lane = t & 31;
    const int gid = lane >> 2, tig = lane & 3;
    const int M0  = (wid & 3) * 32;
    const int nc0 = (wid >> 2) * 64;

    {
        float d[2][2][4][4];

        // ===== gamma layer 2 (MMA, weights pre-scaled by log2e) =====
        gamma_mma<2>(g_w2i, g_b2s, att2v, M0, nc0, gid, tig, d);
        __syncthreads();   // att2 fully read by ALL warps before aliased overwrite
#pragma unroll
        for (int mt = 0; mt < 2; ++mt)
#pragma unroll
        for (int ng = 0; ng < 2; ++ng)
#pragma unroll
        for (int nt = 0; nt < 4; ++nt) {
            int m = M0 + mt * 16 + gid;
            int n = nc0 + ng * 32 + nt * 8 + 2 * tig;
            *(float2*)&att_f[m][n]     = make_float2(d[mt][ng][nt][0], d[mt][ng][nt][1]);
            *(float2*)&att_f[m + 8][n] = make_float2(d[mt][ng][nt][2], d[mt][ng][nt][3]);
        }
    }
    __syncthreads();

    // ---- softmax over channels: float2 col-pairs, 4 row-groups, raw ex2 ----
    {
        const int cp = t & 63, h = t >> 6;   // col pair, 32-row group
        const int col = 2 * cp;
        float m0 = -3.4e38f, m1 = -3.4e38f;
#pragma unroll 8
        for (int i = h * 32; i < h * 32 + 32; ++i) {
            float2 v = *(float2*)&att_f[i][col];
            m0 = fmaxf(m0, v.x); m1 = fmaxf(m1, v.y);
        }
        *(float2*)&smp4[h][col] = make_float2(m0, m1);
        __syncthreads();
        float2 p0 = *(float2*)&smp4[0][col];
        float2 p1 = *(float2*)&smp4[1][col];
        float2 p2 = *(float2*)&smp4[2][col];
        float2 p3 = *(float2*)&smp4[3][col];
        float mmx = fmaxf(fmaxf(p0.x, p1.x), fmaxf(p2.x, p3.x));
        float mmy = fmaxf(fmaxf(p0.y, p1.y), fmaxf(p2.y, p3.y));
        float s0 = 0.0f, s1 = 0.0f;
#pragma unroll 4
        for (int i = h * 32; i < h * 32 + 32; ++i) {
            float2 v = *(float2*)&att_f[i][col];
            float e0 = ex2f(v.x - mmx);
            float e1 = ex2f(v.y - mmy);
            *(float2*)&att_f[i][col] = make_float2(e0, e1);
            s0 += e0; s1 += e1;
        }
        *(float2*)&sms4[h][col] = make_float2(s0, s1);
        __syncthreads();
        if (h == 0) {
            float2 q0 = *(float2*)&sms4[0][col];
            float2 q1 = *(float2*)&sms4[1][col];
            float2 q2 = *(float2*)&sms4[2][col];
            float2 q3 = *(float2*)&sms4[3][col];
            sminv[col]     = 1.0f / (q0.x + q1.x + q2.x + q3.x);
            sminv[col + 1] = 1.0f / (q0.y + q1.y + q2.y + q3.y);
        }
        __syncthreads();
    }

    // ---- epilogue: out = sum_k softmax * (V7.g), col-pairs, float2 loads ----
    {
        const int oa = c, ob = c + 64;
        const float aa0 = alpha_w[oa * 3], aa1 = alpha_w[oa * 3 + 1], aa2 = alpha_w[oa * 3 + 2];
        const float ab0 = alpha_w[ob * 3], ab1 = alpha_w[ob * 3 + 1], ab2 = alpha_w[ob * 3 + 2];
        const float s2a0 = s2_w[oa * 3], s2a1 = s2_w[oa * 3 + 1], s2a2 = s2_w[oa * 3 + 2];
        const float s2b0 = s2_w[ob * 3], s2b1 = s2_w[ob * 3 + 1], s2b2 = s2_w[ob * 3 + 2];
        const float ca = alpha_b[oa] + s2_b[oa];
        const float cb = alpha_b[ob] + s2_b[ob];

        float o0a = 0.0f, o1a = 0.0f, o0b = 0.0f, o1b = 0.0f;
#pragma unroll
        for (int j2 = 0; j2 < 16; ++j2) {
            int col = cg * 32 + 2 * j2;
            float4 gl0 = gsh[col * 2],     gh0 = gsh[col * 2 + 1];
            float4 gl1 = gsh[col * 2 + 2], gh1 = gsh[col * 2 + 3];
            float va0 = aa0 * gl0.x + aa1 * gl0.y + aa2 * gl0.z + s2a0 * gl0.w
                      + s2a1 * gh0.x + s2a2 * gh0.y + ca;
            float vb0 = ab0 * gl0.x + ab1 * gl0.y + ab2 * gl0.z + s2b0 * gl0.w
                      + s2b1 * gh0.x + s2b2 * gh0.y + cb;
            float va1 = aa0 * gl1.x + aa1 * gl1.y + aa2 * gl1.z + s2a0 * gl1.w
                      + s2a1 * gh1.x + s2a2 * gh1.y + ca;
            float vb1 = ab0 * gl1.x + ab1 * gl1.y + ab2 * gl1.z + s2b0 * gl1.w
                      + s2b1 * gh1.x + s2b2 * gh1.y + cb;
            float2 iv = *(float2*)&sminv[col];
            float2 ea = *(float2*)&att_f[oa][col];
            float2 eb = *(float2*)&att_f[ob][col];
            float pa = ea.x * iv.x * va0 + ea.y * iv.y * va1;
            float pb = eb.x * iv.x * vb0 + eb.y * iv.y * vb1;
            if (j2 < 8) { o0a += pa; o0b += pb; }
            else        { o1a += pa; o1b += pb; }
        }
        int p0 = cg * 2;
        out[(size_t)(base + p0) * NC + oa]     = o0a;
        out[(size_t)(base + p0) * NC + ob]     = o0b;
        out[(size_t)(base + p0 + 1) * NC + oa] = o1a;
        out[(size_t)(base + p0 + 1) * NC + ob] = o1b;
    }
}

// ---------------------------------------------------------------------------
extern "C" void kernel_launch(void* const* d_in, const int* in_sizes, int n_in,
                              void* d_out, int out_size)
{
    const float* coords   = (const float*)d_in[0];
    const float* features = (const float*)d_in[1];
    const float* phi_w    = (const float*)d_in[2];
    const float* phi_b    = (const float*)d_in[3];
    const float* psi_w    = (const float*)d_in[4];
    const float* psi_b    = (const float*)d_in[5];
    const float* g1_w     = (const float*)d_in[6];
    const float* g1_b     = (const float*)d_in[7];
    const float* g2_w     = (const float*)d_in[8];
    const float* g2_b     = (const float*)d_in[9];
    const float* s1_w     = (const float*)d_in[10];
    const float* s1_b     = (const float*)d_in[11];
    const float* s2_w     = (const float*)d_in[12];
    const float* s2_b     = (const float*)d_in[13];
    const float* alpha_w  = (const float*)d_in[14];
    const float* alpha_b  = (const float*)d_in[15];
    float* out = (float*)d_out;

    cudaFuncSetAttribute(pt_kernel, cudaFuncAttributeMaxDynamicSharedMemorySize, SM_TOTAL);

    setup_kernel<<<144, 256>>>(coords, g1_w, g2_w, phi_w,
                               g1_b, g2_b, psi_w, psi_b, s2_w, s2_b);
    phi_kernel<<<NB * NP / 32, 128>>>(features, phi_b);
    knn_kernel<<<NB * NP * 32 / 256, 256>>>();
    pt_kernel<<<NB * NP / 8, 256, SM_TOTAL>>>(s1_w, s1_b,
                                              s2_w, s2_b, alpha_w, alpha_b, out);
}